// round 9
// baseline (speedup 1.0000x reference)
#include <cuda_runtime.h>
#include <cuda_bf16.h>
#include <math.h>
#include <stdint.h>

// ---------------- problem constants ----------------
constexpr int NODES = 50000;
constexpr int EDGES = 500000;
constexpr int EP    = EDGES + NODES;   // with self loops = 550000
constexpr int NGRAPH = 64;
constexpr int SC = 96;
constexpr int EMB_D = 32;
constexpr int IN_DIM = 256;            // 96 + 5*32
constexpr int CH = 128;                // hidden channels
constexpr int H1 = 4;                  // heads conv1
constexpr int HC1 = H1 * CH;           // 512
constexpr int NCLS = 5;

// ---------------- scratch (static device memory; no allocation) ----------------
__device__ __nv_bfloat16 g_fh[(size_t)NODES * IN_DIM];   // feats hi
__device__ __nv_bfloat16 g_fl[(size_t)NODES * IN_DIM];   // feats lo
__device__ __nv_bfloat16 g_w1th[(size_t)HC1 * IN_DIM];   // W1^T hi [512][256]
__device__ __nv_bfloat16 g_w1tl[(size_t)HC1 * IN_DIM];
__device__ __nv_bfloat16 g_w2th[(size_t)CH * HC1];       // W2^T hi [128][512]
__device__ __nv_bfloat16 g_w2tl[(size_t)CH * HC1];
__device__ float g_h1[(size_t)NODES * HC1];
__device__ __nv_bfloat16 g_o1h[(size_t)NODES * HC1];     // conv1 output hi
__device__ __nv_bfloat16 g_o1l[(size_t)NODES * HC1];     // conv1 output lo
__device__ float g_as1[NODES * H1];
__device__ float g_ad1[NODES * H1];
__device__ float g_h2[(size_t)NODES * CH];
__device__ float g_as2[NODES];
__device__ float g_ad2[NODES];
__device__ float g_pool[NGRAPH * CH];
// CSR build
__device__ int g_deg[NODES];
__device__ int g_pos[NODES];
__device__ int g_off[NODES + 1];
__device__ int g_csr_src[EP];

// ---------------- helpers ----------------
__device__ __forceinline__ uint32_t smem_u32(const void* p) {
    uint32_t a;
    asm("{ .reg .u64 t; cvta.to.shared.u64 t, %1; cvt.u32.u64 %0, t; }"
        : "=r"(a) : "l"(p));
    return a;
}
__device__ __forceinline__ void atomicMaxF(float* addr, float v) {
    if (v >= 0.f) atomicMax((int*)addr, __float_as_int(v));
    else          atomicMin((unsigned int*)addr, __float_as_uint(v));
}
__device__ __forceinline__ void split_bf16(float v, __nv_bfloat16& h, __nv_bfloat16& l) {
    h = __float2bfloat16(v);
    l = __float2bfloat16(v - __bfloat162float(h));
}

__global__ void fill_f_kernel(float* p, float v, int n) {
    int t = blockIdx.x * blockDim.x + threadIdx.x;
    if (t < n) p[t] = v;
}
__global__ void fill_i_kernel(int* p, int v, int n) {
    int t = blockIdx.x * blockDim.x + threadIdx.x;
    if (t < n) p[t] = v;
}

// ---------------- weight transpose + split: T[n][k] = W[k][n] ----------------
__global__ void prep_w_kernel(const float* __restrict__ W,
                              __nv_bfloat16* __restrict__ Th, __nv_bfloat16* __restrict__ Tl,
                              int K, int N)
{
    int i = blockIdx.x * blockDim.x + threadIdx.x;
    if (i >= K * N) return;
    int n = i / K, k = i - n * K;
    float v = W[(size_t)k * N + n];
    __nv_bfloat16 h, l; split_bf16(v, h, l);
    Th[i] = h; Tl[i] = l;
}

// ---------------- CSR build ----------------
__global__ void deg_kernel(const int* __restrict__ ei) {
    int e = blockIdx.x * blockDim.x + threadIdx.x;
    if (e >= EP) return;
    int d = (e < EDGES) ? ei[EDGES + e] : e - EDGES;
    atomicAdd(&g_deg[d], 1);
}

__global__ void scan_kernel() {
    const int CHK = (NODES + 1 + 1023) / 1024;
    __shared__ int s[1024];
    int t = threadIdx.x;
    int base = t * CHK;
    int sum = 0;
    for (int i = 0; i < CHK; i++) {
        int idx = base + i;
        if (idx < NODES) sum += g_deg[idx];
    }
    s[t] = sum; __syncthreads();
    for (int off = 1; off < 1024; off <<= 1) {
        int v = (t >= off) ? s[t - off] : 0;
        __syncthreads();
        s[t] += v;
        __syncthreads();
    }
    int run = (t == 0) ? 0 : s[t - 1];
    for (int i = 0; i < CHK; i++) {
        int idx = base + i;
        if (idx < NODES) { g_off[idx] = run; run += g_deg[idx]; }
        else if (idx == NODES) g_off[idx] = run;
    }
}

__global__ void scatter_kernel(const int* __restrict__ ei) {
    int e = blockIdx.x * blockDim.x + threadIdx.x;
    if (e >= EP) return;
    int s_, d_;
    if (e < EDGES) { s_ = ei[e]; d_ = ei[EDGES + e]; } else { s_ = d_ = e - EDGES; }
    int p = g_off[d_] + atomicAdd(&g_pos[d_], 1);
    g_csr_src[p] = s_;
}

// ---------------- feature build + layernorm -> bf16 hi/lo ----------------
__global__ void build_feats_kernel(
    const float* __restrict__ xs,
    const int* __restrict__ xop, const int* __restrict__ xsrc,
    const int* __restrict__ xsink, const int* __restrict__ xstr,
    const int* __restrict__ xpay,
    const float* __restrict__ eop, const float* __restrict__ esrc,
    const float* __restrict__ esink, const float* __restrict__ estr,
    const float* __restrict__ epay,
    const float* __restrict__ lng, const float* __restrict__ lnb)
{
    int n = blockIdx.x;
    int t = threadIdx.x;   // 0..255
    float v;
    if (t < SC) {
        v = xs[(size_t)n * SC + t];
    } else {
        int gidx = (t - SC) >> 5;
        int dim  = (t - SC) & 31;
        const int* idxp; const float* tab; int L;
        switch (gidx) {
            case 0: idxp = xop  + (size_t)n * 16; tab = eop;  L = 16; break;
            case 1: idxp = xsrc + (size_t)n * 8;  tab = esrc; L = 8;  break;
            case 2: idxp = xsink+ (size_t)n * 8;  tab = esink;L = 8;  break;
            case 3: idxp = xstr + (size_t)n * 8;  tab = estr; L = 8;  break;
            default:idxp = xpay + (size_t)n * 8;  tab = epay; L = 8;  break;
        }
        float sum = 0.f, cnt = 0.f;
        for (int l = 0; l < L; l++) {
            int id = idxp[l];
            if (id != 0) { sum += tab[(size_t)id * EMB_D + dim]; cnt += 1.f; }
        }
        v = sum / (cnt + 1e-9f);
    }
    __shared__ float red[IN_DIM];
    red[t] = v; __syncthreads();
    for (int s = 128; s; s >>= 1) { if (t < s) red[t] += red[t + s]; __syncthreads(); }
    float mu = red[0] * (1.f / IN_DIM);
    __syncthreads();
    float dv = v - mu;
    red[t] = dv * dv; __syncthreads();
    for (int s = 128; s; s >>= 1) { if (t < s) red[t] += red[t + s]; __syncthreads(); }
    float var = red[0] * (1.f / IN_DIM);
    float r = rsqrtf(var + 1e-5f);
    float o = dv * r * lng[t] + lnb[t];
    __nv_bfloat16 h, l; split_bf16(o, h, l);
    g_fh[(size_t)n * IN_DIM + t] = h;
    g_fl[(size_t)n * IN_DIM + t] = l;
}

// ---------------- mma.sync helpers ----------------
__device__ __forceinline__ void ldmat_x4(uint32_t* r, uint32_t addr) {
    asm volatile("ldmatrix.sync.aligned.m8n8.x4.shared.b16 {%0,%1,%2,%3}, [%4];"
        : "=r"(r[0]), "=r"(r[1]), "=r"(r[2]), "=r"(r[3]) : "r"(addr));
}
__device__ __forceinline__ void ldmat_x2(uint32_t* r, uint32_t addr) {
    asm volatile("ldmatrix.sync.aligned.m8n8.x2.shared.b16 {%0,%1}, [%2];"
        : "=r"(r[0]), "=r"(r[1]) : "r"(addr));
}
__device__ __forceinline__ void mma16816(float* c, const uint32_t* a, const uint32_t* b) {
    asm volatile(
        "mma.sync.aligned.m16n8k16.row.col.f32.bf16.bf16.f32 "
        "{%0,%1,%2,%3}, {%4,%5,%6,%7}, {%8,%9}, {%0,%1,%2,%3};"
        : "+f"(c[0]), "+f"(c[1]), "+f"(c[2]), "+f"(c[3])
        : "r"(a[0]), "r"(a[1]), "r"(a[2]), "r"(a[3]), "r"(b[0]), "r"(b[1]));
}
__device__ __forceinline__ void cpasync16(uint32_t dst, const void* src, uint32_t src_sz) {
    asm volatile("cp.async.cg.shared.global [%0], [%1], 16, %2;"
        :: "r"(dst), "l"(src), "r"(src_sz) : "memory");
}
#define CP_COMMIT() asm volatile("cp.async.commit_group;" ::: "memory")
#define CP_WAIT(N)  asm volatile("cp.async.wait_group %0;" :: "n"(N) : "memory")

// ---------------- bf16x3 HMMA GEMM, 128x128 tile, cp.async 2-stage ----------
// C[M,N] = (Ah+Al)[M,K] @ (Bh+Bl)^T, B^T given as [N][K] K-major.
// Fused: as_[r*heads+hh] = C_row . att_s[hh]; ad_ likewise (tile width == CH).
constexpr int GBK = 32;                // K chunk
constexpr int GLD = GBK + 8;           // smem row stride (halves); 80B, 16B-aligned
constexpr int TSZ = 128 * GLD;         // halves per tile
constexpr int GEMM_SMEM_BYTES = 2 * 4 * TSZ * 2;   // 2 stages x 4 tiles

__global__ void __launch_bounds__(256)
gemm_bf3_kernel(const __nv_bfloat16* __restrict__ gAh, const __nv_bfloat16* __restrict__ gAl,
                const __nv_bfloat16* __restrict__ gBh, const __nv_bfloat16* __restrict__ gBl,
                float* __restrict__ C,
                const float* __restrict__ att_s, const float* __restrict__ att_d,
                float* __restrict__ as_, float* __restrict__ ad_,
                int M, int N, int K, int heads)
{
    extern __shared__ __align__(16) __nv_bfloat16 dsm[];
    __shared__ float s_sdot[128];
    __shared__ float s_ddot[128];

    int tid = threadIdx.x;
    int lane = tid & 31;
    int warp = tid >> 5;          // 0..7
    int warp_m = warp >> 2;       // 0..1  (64 rows each)
    int warp_n = warp & 3;        // 0..3  (32 cols each)
    int row0 = blockIdx.y * 128;
    int col0 = blockIdx.x * 128;
    int hh = blockIdx.x;

    if (tid < 128) { s_sdot[tid] = 0.f; s_ddot[tid] = 0.f; }

    int avalid = M - row0; if (avalid > 128) avalid = 128;

    float acc[4][4][4];
    #pragma unroll
    for (int a = 0; a < 4; a++)
        #pragma unroll
        for (int b = 0; b < 4; b++)
            #pragma unroll
            for (int c = 0; c < 4; c++) acc[a][b][c] = 0.f;

    // per-thread load coordinates: 8 chunks of 16B per tile set
    // i in [0, 2048): tile = i>>9, pos = i&511, r = pos>>2, c = (pos&3)*8
    auto issue_loads = [&](int kc, int stage) {
        int k0 = kc * GBK;
        __nv_bfloat16* S = dsm + stage * 4 * TSZ;
        #pragma unroll
        for (int l = 0; l < 8; l++) {
            int i = tid + l * 256;
            int tile = i >> 9;
            int pos = i & 511;
            int r = pos >> 2, c = (pos & 3) << 3;
            uint32_t dst = smem_u32(S + tile * TSZ + r * GLD + c);
            const __nv_bfloat16* g; int rbase; uint32_t sz;
            if (tile < 2) {
                g = (tile == 0) ? gAh : gAl; rbase = row0;
                sz = (r < avalid) ? 16u : 0u;
            } else {
                g = (tile == 2) ? gBh : gBl; rbase = col0;
                sz = 16u;
            }
            cpasync16(dst, g + (size_t)(rbase + r) * K + k0 + c, sz);
        }
        CP_COMMIT();
    };

    // ldmatrix per-lane source coordinates
    int lar = lane & 15;                 // A row within 16-block
    int lac = (lane >> 4) << 3;          // A col 0/8
    int lbr = lane & 7;                  // B row within 8-block
    int lbc = ((lane >> 3) & 1) << 3;    // B col 0/8

    int nchunks = K / GBK;
    issue_loads(0, 0);
    for (int kc = 0; kc < nchunks; kc++) {
        int stage = kc & 1;
        if (kc + 1 < nchunks) {
            issue_loads(kc + 1, stage ^ 1);
            CP_WAIT(1);
        } else {
            CP_WAIT(0);
        }
        __syncthreads();
        __nv_bfloat16* S = dsm + stage * 4 * TSZ;
        __nv_bfloat16* pAh = S;
        __nv_bfloat16* pAl = S + TSZ;
        __nv_bfloat16* pBh = S + 2 * TSZ;
        __nv_bfloat16* pBl = S + 3 * TSZ;
        #pragma unroll
        for (int k16 = 0; k16 < GBK / 16; k16++) {
            uint32_t ah[4][4], al[4][4], bh[4][2], bl[4][2];
            #pragma unroll
            for (int mf = 0; mf < 4; mf++) {
                int r = warp_m * 64 + mf * 16 + lar;
                int cc = k16 * 16 + lac;
                ldmat_x4(ah[mf], smem_u32(pAh + r * GLD + cc));
                ldmat_x4(al[mf], smem_u32(pAl + r * GLD + cc));
            }
            #pragma unroll
            for (int nf = 0; nf < 4; nf++) {
                int r = warp_n * 32 + nf * 8 + lbr;
                int cc = k16 * 16 + lbc;
                ldmat_x2(bh[nf], smem_u32(pBh + r * GLD + cc));
                ldmat_x2(bl[nf], smem_u32(pBl + r * GLD + cc));
            }
            #pragma unroll
            for (int mf = 0; mf < 4; mf++)
                #pragma unroll
                for (int nf = 0; nf < 4; nf++) {
                    mma16816(acc[mf][nf], ah[mf], bh[nf]);
                    mma16816(acc[mf][nf], ah[mf], bl[nf]);
                    mma16816(acc[mf][nf], al[mf], bh[nf]);
                }
        }
        __syncthreads();
    }

    // epilogue: C store + attention dot reduction
    float sa[4][2], da[4][2];
    #pragma unroll
    for (int nf = 0; nf < 4; nf++) {
        int c = warp_n * 32 + nf * 8 + (lane & 3) * 2;
        sa[nf][0] = att_s[hh * CH + c];     sa[nf][1] = att_s[hh * CH + c + 1];
        da[nf][0] = att_d[hh * CH + c];     da[nf][1] = att_d[hh * CH + c + 1];
    }
    #pragma unroll
    for (int mf = 0; mf < 4; mf++) {
        int r0l = warp_m * 64 + mf * 16 + (lane >> 2);
        int r1l = r0l + 8;
        int gr0 = row0 + r0l, gr1 = row0 + r1l;
        float sd0 = 0.f, dd0 = 0.f, sd1 = 0.f, dd1 = 0.f;
        #pragma unroll
        for (int nf = 0; nf < 4; nf++) {
            float c0 = acc[mf][nf][0], c1 = acc[mf][nf][1];
            float c2 = acc[mf][nf][2], c3 = acc[mf][nf][3];
            int gc = col0 + warp_n * 32 + nf * 8 + (lane & 3) * 2;
            if (gr0 < M) *(float2*)&C[(size_t)gr0 * N + gc] = make_float2(c0, c1);
            if (gr1 < M) *(float2*)&C[(size_t)gr1 * N + gc] = make_float2(c2, c3);
            sd0 += c0 * sa[nf][0] + c1 * sa[nf][1];
            dd0 += c0 * da[nf][0] + c1 * da[nf][1];
            sd1 += c2 * sa[nf][0] + c3 * sa[nf][1];
            dd1 += c2 * da[nf][0] + c3 * da[nf][1];
        }
        #pragma unroll
        for (int o = 1; o <= 2; o <<= 1) {
            sd0 += __shfl_xor_sync(0xffffffffu, sd0, o);
            dd0 += __shfl_xor_sync(0xffffffffu, dd0, o);
            sd1 += __shfl_xor_sync(0xffffffffu, sd1, o);
            dd1 += __shfl_xor_sync(0xffffffffu, dd1, o);
        }
        if ((lane & 3) == 0) {
            atomicAdd(&s_sdot[r0l], sd0);
            atomicAdd(&s_ddot[r0l], dd0);
            atomicAdd(&s_sdot[r1l], sd1);
            atomicAdd(&s_ddot[r1l], dd1);
        }
    }
    __syncthreads();
    if (tid < 128 && row0 + tid < M) {
        as_[(row0 + tid) * heads + hh] = s_sdot[tid];
        ad_[(row0 + tid) * heads + hh] = s_ddot[tid];
    }
}

// ---------------- conv1: fused softmax + aggregation + bias/ELU -> bf16 hi/lo ----
// block per node, warp w = head w. 3 passes over in-edges: max, sum, aggregate.
__global__ void __launch_bounds__(128)
agg1_fused_kernel(const float* __restrict__ h,
                  const float* __restrict__ as_, const float* __restrict__ ad_,
                  const float* __restrict__ bias,
                  __nv_bfloat16* __restrict__ outh, __nv_bfloat16* __restrict__ outl)
{
    int node = blockIdx.x;
    int t = threadIdx.x;
    int w = t >> 5;
    int lane = t & 31;
    int s0 = g_off[node], s1 = g_off[node + 1];
    float adv = ad_[node * H1 + w];

    // pass 1: max
    float mx = -3.4e38f;
    for (int p = s0 + lane; p < s1; p += 32) {
        float v = as_[g_csr_src[p] * H1 + w] + adv;
        v = v > 0.f ? v : 0.2f * v;
        mx = fmaxf(mx, v);
    }
    #pragma unroll
    for (int o = 16; o; o >>= 1) mx = fmaxf(mx, __shfl_xor_sync(0xffffffffu, mx, o));
    // pass 2: sum
    float sum = 0.f;
    for (int p = s0 + lane; p < s1; p += 32) {
        float v = as_[g_csr_src[p] * H1 + w] + adv;
        v = v > 0.f ? v : 0.2f * v;
        sum += __expf(v - mx);
    }
    #pragma unroll
    for (int o = 16; o; o >>= 1) sum += __shfl_xor_sync(0xffffffffu, sum, o);
    float inv = 1.f / (sum + 1e-16f);

    // pass 3: chunked aggregate, alpha computed by one lane per edge, shfl-broadcast
    int col = w * CH + lane * 4;
    float4 acc = make_float4(0.f, 0.f, 0.f, 0.f);
    for (int base = s0; base < s1; base += 32) {
        int p = base + lane;
        float a = 0.f; int src = 0;
        if (p < s1) {
            src = g_csr_src[p];
            float v = as_[src * H1 + w] + adv;
            v = v > 0.f ? v : 0.2f * v;
            a = __expf(v - mx);
        }
        int cnt = s1 - base; if (cnt > 32) cnt = 32;
        for (int j = 0; j < cnt; j++) {
            float aj = __shfl_sync(0xffffffffu, a, j);
            int sj = __shfl_sync(0xffffffffu, src, j);
            float4 hv = *(const float4*)&h[(size_t)sj * HC1 + col];
            acc.x += aj * hv.x; acc.y += aj * hv.y;
            acc.z += aj * hv.z; acc.w += aj * hv.w;
        }
    }
    float4 b = *(const float4*)&bias[col];
    float4 v;
    v.x = acc.x * inv + b.x; v.y = acc.y * inv + b.y;
    v.z = acc.z * inv + b.z; v.w = acc.w * inv + b.w;
    v.x = v.x > 0.f ? v.x : expm1f(v.x);
    v.y = v.y > 0.f ? v.y : expm1f(v.y);
    v.z = v.z > 0.f ? v.z : expm1f(v.z);
    v.w = v.w > 0.f ? v.w : expm1f(v.w);
    size_t o = (size_t)node * HC1 + col;
    __nv_bfloat16 hx, lx;
    split_bf16(v.x, hx, lx); outh[o + 0] = hx; outl[o + 0] = lx;
    split_bf16(v.y, hx, lx); outh[o + 1] = hx; outl[o + 1] = lx;
    split_bf16(v.z, hx, lx); outh[o + 2] = hx; outl[o + 2] = lx;
    split_bf16(v.w, hx, lx); outh[o + 3] = hx; outl[o + 3] = lx;
}

// ---------------- conv2: fused softmax + aggregation + bias/ELU + maxpool ----
__global__ void agg2_fused_kernel(const float* __restrict__ h,
                                  const float* __restrict__ as_, const float* __restrict__ ad_,
                                  const float* __restrict__ bias,
                                  const int* __restrict__ batch)
{
    int warp = (blockIdx.x * blockDim.x + threadIdx.x) >> 5;
    int lane = threadIdx.x & 31;
    if (warp >= NODES) return;
    int node = warp;
    int s0 = g_off[node], s1 = g_off[node + 1];
    float adv = ad_[node];

    float mx = -3.4e38f;
    for (int p = s0 + lane; p < s1; p += 32) {
        float v = as_[g_csr_src[p]] + adv;
        v = v > 0.f ? v : 0.2f * v;
        mx = fmaxf(mx, v);
    }
    #pragma unroll
    for (int o = 16; o; o >>= 1) mx = fmaxf(mx, __shfl_xor_sync(0xffffffffu, mx, o));
    float sum = 0.f;
    for (int p = s0 + lane; p < s1; p += 32) {
        float v = as_[g_csr_src[p]] + adv;
        v = v > 0.f ? v : 0.2f * v;
        sum += __expf(v - mx);
    }
    #pragma unroll
    for (int o = 16; o; o >>= 1) sum += __shfl_xor_sync(0xffffffffu, sum, o);
    float inv = 1.f / (sum + 1e-16f);

    int col = lane * 4;
    float4 acc = make_float4(0.f, 0.f, 0.f, 0.f);
    for (int base = s0; base < s1; base += 32) {
        int p = base + lane;
        float a = 0.f; int src = 0;
        if (p < s1) {
            src = g_csr_src[p];
            float v = as_[src] + adv;
            v = v > 0.f ? v : 0.2f * v;
            a = __expf(v - mx);
        }
        int cnt = s1 - base; if (cnt > 32) cnt = 32;
        for (int j = 0; j < cnt; j++) {
            float aj = __shfl_sync(0xffffffffu, a, j);
            int sj = __shfl_sync(0xffffffffu, src, j);
            float4 hv = *(const float4*)&h[(size_t)sj * CH + col];
            acc.x += aj * hv.x; acc.y += aj * hv.y;
            acc.z += aj * hv.z; acc.w += aj * hv.w;
        }
    }
    float4 b = *(const float4*)&bias[col];
    float4 v;
    v.x = acc.x * inv + b.x; v.y = acc.y * inv + b.y;
    v.z = acc.z * inv + b.z; v.w = acc.w * inv + b.w;
    v.x = v.x > 0.f ? v.x : expm1f(v.x);
    v.y = v.y > 0.f ? v.y : expm1f(v.y);
    v.z = v.z > 0.f ? v.z : expm1f(v.z);
    v.w = v.w > 0.f ? v.w : expm1f(v.w);
    float* pp = &g_pool[batch[node] * CH + col];
    atomicMaxF(pp + 0, v.x);
    atomicMaxF(pp + 1, v.y);
    atomicMaxF(pp + 2, v.z);
    atomicMaxF(pp + 3, v.w);
}

// ---------------- classifier head ----------------
__global__ void classify_kernel(const float* __restrict__ Wc1, const float* __restrict__ bc1,
                                const float* __restrict__ Wc2, const float* __restrict__ bc2,
                                float* __restrict__ out)
{
    __shared__ float xp[CH];
    __shared__ float hc[CH / 2];
    int gg = blockIdx.x;
    int t = threadIdx.x;   // 0..63
    xp[t]      = g_pool[gg * CH + t];
    xp[t + 64] = g_pool[gg * CH + 64 + t];
    __syncthreads();
    float acc = bc1[t];
    for (int k = 0; k < CH; k++) acc += xp[k] * Wc1[k * (CH / 2) + t];
    hc[t] = fmaxf(acc, 0.f);
    __syncthreads();
    if (t < NCLS) {
        float o = bc2[t];
        for (int k = 0; k < CH / 2; k++) o += hc[k] * Wc2[k * NCLS + t];
        out[gg * NCLS + t] = o;
    }
}

// ---------------- launch ----------------
extern "C" void kernel_launch(void* const* d_in, const int* in_sizes, int n_in,
                              void* d_out, int out_size)
{
    const float* xs    = (const float*)d_in[0];
    const int*   xop   = (const int*)d_in[1];
    const int*   xsrc  = (const int*)d_in[2];
    const int*   xsink = (const int*)d_in[3];
    const int*   xstr  = (const int*)d_in[4];
    const int*   xpay  = (const int*)d_in[5];
    const int*   ei    = (const int*)d_in[6];
    const int*   batch = (const int*)d_in[7];
    const float* eop   = (const float*)d_in[8];
    const float* esrc  = (const float*)d_in[9];
    const float* esink = (const float*)d_in[10];
    const float* estr  = (const float*)d_in[11];
    const float* epay  = (const float*)d_in[12];
    const float* lng   = (const float*)d_in[13];
    const float* lnb   = (const float*)d_in[14];
    const float* W1    = (const float*)d_in[15];
    const float* att_s1= (const float*)d_in[16];
    const float* att_d1= (const float*)d_in[17];
    const float* b1    = (const float*)d_in[18];
    const float* W2    = (const float*)d_in[19];
    const float* att_s2= (const float*)d_in[20];
    const float* att_d2= (const float*)d_in[21];
    const float* b2    = (const float*)d_in[22];
    const float* Wc1   = (const float*)d_in[23];
    const float* bc1   = (const float*)d_in[24];
    const float* Wc2   = (const float*)d_in[25];
    const float* bc2   = (const float*)d_in[26];
    float* out = (float*)d_out;

    __nv_bfloat16 *fh, *fl, *w1th, *w1tl, *w2th, *w2tl, *o1h, *o1l;
    float *h1, *as1, *ad1;
    float *h2, *as2, *ad2, *pool;
    int *deg, *pos;
    cudaGetSymbolAddress((void**)&fh,    g_fh);
    cudaGetSymbolAddress((void**)&fl,    g_fl);
    cudaGetSymbolAddress((void**)&w1th,  g_w1th);
    cudaGetSymbolAddress((void**)&w1tl,  g_w1tl);
    cudaGetSymbolAddress((void**)&w2th,  g_w2th);
    cudaGetSymbolAddress((void**)&w2tl,  g_w2tl);
    cudaGetSymbolAddress((void**)&o1h,   g_o1h);
    cudaGetSymbolAddress((void**)&o1l,   g_o1l);
    cudaGetSymbolAddress((void**)&h1,    g_h1);
    cudaGetSymbolAddress((void**)&as1,   g_as1);
    cudaGetSymbolAddress((void**)&ad1,   g_ad1);
    cudaGetSymbolAddress((void**)&h2,    g_h2);
    cudaGetSymbolAddress((void**)&as2,   g_as2);
    cudaGetSymbolAddress((void**)&ad2,   g_ad2);
    cudaGetSymbolAddress((void**)&pool,  g_pool);
    cudaGetSymbolAddress((void**)&deg,   g_deg);
    cudaGetSymbolAddress((void**)&pos,   g_pos);

    const float NEG_INF = -__builtin_huge_valf();
    auto blocks = [](long long n, int bs) { return (unsigned)((n + bs - 1) / bs); };

    cudaFuncSetAttribute(gemm_bf3_kernel, cudaFuncAttributeMaxDynamicSharedMemorySize,
                         GEMM_SMEM_BYTES);

    // scratch init
    fill_i_kernel<<<blocks(NODES, 256), 256>>>(deg, 0, NODES);
    fill_i_kernel<<<blocks(NODES, 256), 256>>>(pos, 0, NODES);
    fill_f_kernel<<<blocks(NGRAPH * CH, 256), 256>>>(pool, NEG_INF, NGRAPH * CH);

    // CSR build
    deg_kernel<<<blocks(EP, 256), 256>>>(ei);
    scan_kernel<<<1, 1024>>>();
    scatter_kernel<<<blocks(EP, 256), 256>>>(ei);

    // weight transposes + splits
    prep_w_kernel<<<blocks((long long)IN_DIM * HC1, 256), 256>>>(W1, w1th, w1tl, IN_DIM, HC1);
    prep_w_kernel<<<blocks((long long)HC1 * CH, 256), 256>>>(W2, w2th, w2tl, HC1, CH);

    // 1. features + layernorm -> bf16 hi/lo
    build_feats_kernel<<<NODES, 256>>>(xs, xop, xsrc, xsink, xstr, xpay,
                                       eop, esrc, esink, estr, epay, lng, lnb);

    // 2. conv1: HMMA GEMM (+fused attn scores), fused softmax+aggregate
    {
        dim3 grid(HC1 / 128, (NODES + 127) / 128);
        gemm_bf3_kernel<<<grid, 256, GEMM_SMEM_BYTES>>>(fh, fl, w1th, w1tl, h1,
                                                        att_s1, att_d1, as1, ad1,
                                                        NODES, HC1, IN_DIM, H1);
    }
    agg1_fused_kernel<<<NODES, 128>>>(h1, as1, ad1, b1, o1h, o1l);

    // 3. conv2
    {
        dim3 grid(CH / 128, (NODES + 127) / 128);
        gemm_bf3_kernel<<<grid, 256, GEMM_SMEM_BYTES>>>(o1h, o1l, w2th, w2tl, h2,
                                                        att_s2, att_d2, as2, ad2,
                                                        NODES, CH, HC1, 1);
    }
    agg2_fused_kernel<<<blocks((long long)NODES * 32, 256), 256>>>(h2, as2, ad2, b2, batch);

    // 4. classifier
    classify_kernel<<<NGRAPH, 64>>>(Wc1, bc1, Wc2, bc2, out);
}

// round 10
// speedup vs baseline: 1.1313x; 1.1313x over previous
#include <cuda_runtime.h>
#include <cuda_bf16.h>
#include <math.h>
#include <stdint.h>

// ---------------- problem constants ----------------
constexpr int NODES = 50000;
constexpr int EDGES = 500000;
constexpr int EP    = EDGES + NODES;   // with self loops = 550000
constexpr int NGRAPH = 64;
constexpr int SC = 96;
constexpr int EMB_D = 32;
constexpr int IN_DIM = 256;            // 96 + 5*32
constexpr int CH = 128;                // hidden channels
constexpr int H1 = 4;                  // heads conv1
constexpr int HC1 = H1 * CH;           // 512
constexpr int NCLS = 5;

// ---------------- scratch (static device memory; no allocation) ----------------
__device__ __nv_bfloat16 g_fh[(size_t)NODES * IN_DIM];   // feats hi
__device__ __nv_bfloat16 g_fl[(size_t)NODES * IN_DIM];   // feats lo
__device__ __nv_bfloat16 g_w1th[(size_t)HC1 * IN_DIM];   // W1^T hi [512][256]
__device__ __nv_bfloat16 g_w1tl[(size_t)HC1 * IN_DIM];
__device__ __nv_bfloat16 g_w2th[(size_t)CH * HC1];       // W2^T hi [128][512]
__device__ __nv_bfloat16 g_w2tl[(size_t)CH * HC1];
__device__ float g_h1[(size_t)NODES * HC1];
__device__ __nv_bfloat16 g_o1h[(size_t)NODES * HC1];     // conv1 output hi
__device__ __nv_bfloat16 g_o1l[(size_t)NODES * HC1];     // conv1 output lo
__device__ float g_as1[NODES * H1];
__device__ float g_ad1[NODES * H1];
__device__ float g_inv1[NODES * H1];
__device__ float g_alpha1[(size_t)EP * H1];
__device__ float g_h2[(size_t)NODES * CH];
__device__ float g_as2[NODES];
__device__ float g_ad2[NODES];
__device__ float g_inv2[NODES];
__device__ float g_alpha2[EP];
__device__ float g_pool[NGRAPH * CH];
// CSR build
__device__ int g_deg[NODES];
__device__ int g_pos[NODES];
__device__ int g_off[NODES + 1];
__device__ int g_csr_src[EP];

// ---------------- helpers ----------------
__device__ __forceinline__ uint32_t smem_u32(const void* p) {
    uint32_t a;
    asm("{ .reg .u64 t; cvta.to.shared.u64 t, %1; cvt.u32.u64 %0, t; }"
        : "=r"(a) : "l"(p));
    return a;
}
__device__ __forceinline__ void atomicMaxF(float* addr, float v) {
    if (v >= 0.f) atomicMax((int*)addr, __float_as_int(v));
    else          atomicMin((unsigned int*)addr, __float_as_uint(v));
}
__device__ __forceinline__ void split_bf16(float v, __nv_bfloat16& h, __nv_bfloat16& l) {
    h = __float2bfloat16(v);
    l = __float2bfloat16(v - __bfloat162float(h));
}

// fused scratch init: zero deg+pos, fill pool with -inf
__global__ void init_kernel() {
    int t = blockIdx.x * blockDim.x + threadIdx.x;
    if (t < NODES) { g_deg[t] = 0; g_pos[t] = 0; }
    if (t < NGRAPH * CH) g_pool[t] = -3.4e38f;
}

// ---------------- fused weight transpose + split for W1 and W2 ----------------
__global__ void prep_w_kernel(const float* __restrict__ W1, const float* __restrict__ W2)
{
    int i = blockIdx.x * blockDim.x + threadIdx.x;
    const int N1 = IN_DIM * HC1;             // 131072
    const int N2 = HC1 * CH;                 // 65536
    if (i < N1) {
        int n = i / IN_DIM, k = i - n * IN_DIM;
        float v = W1[(size_t)k * HC1 + n];
        __nv_bfloat16 h, l; split_bf16(v, h, l);
        g_w1th[i] = h; g_w1tl[i] = l;
    } else if (i < N1 + N2) {
        int j = i - N1;
        int n = j / HC1, k = j - n * HC1;
        float v = W2[(size_t)k * CH + n];
        __nv_bfloat16 h, l; split_bf16(v, h, l);
        g_w2th[j] = h; g_w2tl[j] = l;
    }
}

// ---------------- CSR build ----------------
__global__ void deg_kernel(const int* __restrict__ ei) {
    int e = blockIdx.x * blockDim.x + threadIdx.x;
    if (e >= EP) return;
    int d = (e < EDGES) ? ei[EDGES + e] : e - EDGES;
    atomicAdd(&g_deg[d], 1);
}

__global__ void scan_kernel() {
    const int CHK = (NODES + 1 + 1023) / 1024;
    __shared__ int s[1024];
    int t = threadIdx.x;
    int base = t * CHK;
    int sum = 0;
    for (int i = 0; i < CHK; i++) {
        int idx = base + i;
        if (idx < NODES) sum += g_deg[idx];
    }
    s[t] = sum; __syncthreads();
    for (int off = 1; off < 1024; off <<= 1) {
        int v = (t >= off) ? s[t - off] : 0;
        __syncthreads();
        s[t] += v;
        __syncthreads();
    }
    int run = (t == 0) ? 0 : s[t - 1];
    for (int i = 0; i < CHK; i++) {
        int idx = base + i;
        if (idx < NODES) { g_off[idx] = run; run += g_deg[idx]; }
        else if (idx == NODES) g_off[idx] = run;
    }
}

__global__ void scatter_kernel(const int* __restrict__ ei) {
    int e = blockIdx.x * blockDim.x + threadIdx.x;
    if (e >= EP) return;
    int s_, d_;
    if (e < EDGES) { s_ = ei[e]; d_ = ei[EDGES + e]; } else { s_ = d_ = e - EDGES; }
    int p = g_off[d_] + atomicAdd(&g_pos[d_], 1);
    g_csr_src[p] = s_;
}

// ---------------- feature build + layernorm -> bf16 hi/lo ----------------
__global__ void build_feats_kernel(
    const float* __restrict__ xs,
    const int* __restrict__ xop, const int* __restrict__ xsrc,
    const int* __restrict__ xsink, const int* __restrict__ xstr,
    const int* __restrict__ xpay,
    const float* __restrict__ eop, const float* __restrict__ esrc,
    const float* __restrict__ esink, const float* __restrict__ estr,
    const float* __restrict__ epay,
    const float* __restrict__ lng, const float* __restrict__ lnb)
{
    int n = blockIdx.x;
    int t = threadIdx.x;   // 0..255
    int lane = t & 31, warp = t >> 5;
    float v;
    if (t < SC) {
        v = xs[(size_t)n * SC + t];
    } else {
        int gidx = (t - SC) >> 5;
        int dim  = (t - SC) & 31;
        const int* idxp; const float* tab; int L;
        switch (gidx) {
            case 0: idxp = xop  + (size_t)n * 16; tab = eop;  L = 16; break;
            case 1: idxp = xsrc + (size_t)n * 8;  tab = esrc; L = 8;  break;
            case 2: idxp = xsink+ (size_t)n * 8;  tab = esink;L = 8;  break;
            case 3: idxp = xstr + (size_t)n * 8;  tab = estr; L = 8;  break;
            default:idxp = xpay + (size_t)n * 8;  tab = epay; L = 8;  break;
        }
        float sum = 0.f, cnt = 0.f;
        for (int l = 0; l < L; l++) {
            int id = idxp[l];
            if (id != 0) { sum += tab[(size_t)id * EMB_D + dim]; cnt += 1.f; }
        }
        v = sum / (cnt + 1e-9f);
    }
    // warp-shuffle layernorm reductions
    __shared__ float wred[8];
    float ws = v;
    #pragma unroll
    for (int o = 16; o; o >>= 1) ws += __shfl_xor_sync(0xffffffffu, ws, o);
    if (lane == 0) wred[warp] = ws;
    __syncthreads();
    float tot = 0.f;
    #pragma unroll
    for (int i = 0; i < 8; i++) tot += wred[i];
    float mu = tot * (1.f / IN_DIM);
    float dv = v - mu;
    __syncthreads();
    float ws2 = dv * dv;
    #pragma unroll
    for (int o = 16; o; o >>= 1) ws2 += __shfl_xor_sync(0xffffffffu, ws2, o);
    if (lane == 0) wred[warp] = ws2;
    __syncthreads();
    float tot2 = 0.f;
    #pragma unroll
    for (int i = 0; i < 8; i++) tot2 += wred[i];
    float var = tot2 * (1.f / IN_DIM);
    float r = rsqrtf(var + 1e-5f);
    float o = dv * r * lng[t] + lnb[t];
    __nv_bfloat16 h, l; split_bf16(o, h, l);
    g_fh[(size_t)n * IN_DIM + t] = h;
    g_fl[(size_t)n * IN_DIM + t] = l;
}

// ---------------- mma.sync helpers ----------------
__device__ __forceinline__ void ldmat_x4(uint32_t* r, uint32_t addr) {
    asm volatile("ldmatrix.sync.aligned.m8n8.x4.shared.b16 {%0,%1,%2,%3}, [%4];"
        : "=r"(r[0]), "=r"(r[1]), "=r"(r[2]), "=r"(r[3]) : "r"(addr));
}
__device__ __forceinline__ void ldmat_x2(uint32_t* r, uint32_t addr) {
    asm volatile("ldmatrix.sync.aligned.m8n8.x2.shared.b16 {%0,%1}, [%2];"
        : "=r"(r[0]), "=r"(r[1]) : "r"(addr));
}
__device__ __forceinline__ void mma16816(float* c, const uint32_t* a, const uint32_t* b) {
    asm volatile(
        "mma.sync.aligned.m16n8k16.row.col.f32.bf16.bf16.f32 "
        "{%0,%1,%2,%3}, {%4,%5,%6,%7}, {%8,%9}, {%0,%1,%2,%3};"
        : "+f"(c[0]), "+f"(c[1]), "+f"(c[2]), "+f"(c[3])
        : "r"(a[0]), "r"(a[1]), "r"(a[2]), "r"(a[3]), "r"(b[0]), "r"(b[1]));
}

// ---------------- bf16x3 HMMA GEMM 128x128 tile + fused attention scores ----
// (R8 structure: sync smem loads, single buffer, 2 CTAs/SM)
constexpr int GBK = 32;                // K chunk
constexpr int GLD = GBK + 8;           // smem row stride in halves (conflict-free)

__global__ void __launch_bounds__(256, 2)
gemm_bf3_kernel(const __nv_bfloat16* __restrict__ gAh, const __nv_bfloat16* __restrict__ gAl,
                const __nv_bfloat16* __restrict__ gBh, const __nv_bfloat16* __restrict__ gBl,
                float* __restrict__ C,
                const float* __restrict__ att_s, const float* __restrict__ att_d,
                float* __restrict__ as_, float* __restrict__ ad_,
                int M, int N, int K, int heads)
{
    __shared__ __align__(16) __nv_bfloat16 sAh[128][GLD];
    __shared__ __align__(16) __nv_bfloat16 sAl[128][GLD];
    __shared__ __align__(16) __nv_bfloat16 sBh[128][GLD];
    __shared__ __align__(16) __nv_bfloat16 sBl[128][GLD];
    __shared__ float s_sdot[128];
    __shared__ float s_ddot[128];

    int tid = threadIdx.x;
    int lane = tid & 31;
    int warp = tid >> 5;          // 0..7
    int warp_m = warp >> 2;       // 0..1  (64 rows each)
    int warp_n = warp & 3;        // 0..3  (32 cols each)
    int row0 = blockIdx.y * 128;
    int col0 = blockIdx.x * 128;
    int hh = blockIdx.x;

    if (tid < 128) { s_sdot[tid] = 0.f; s_ddot[tid] = 0.f; }

    int avalid = M - row0; if (avalid > 128) avalid = 128;

    float acc[4][4][4];
    #pragma unroll
    for (int a = 0; a < 4; a++)
        #pragma unroll
        for (int b = 0; b < 4; b++)
            #pragma unroll
            for (int c = 0; c < 4; c++) acc[a][b][c] = 0.f;

    int lar = lane & 15;
    int lac = (lane >> 4) << 3;
    int lbr = lane & 7;
    int lbc = ((lane >> 3) & 1) << 3;

    int nchunks = K / GBK;
    for (int kc = 0; kc < nchunks; kc++) {
        int k0 = kc * GBK;
        __syncthreads();
        for (int i = tid; i < 128 * (GBK / 8); i += 256) {
            int r = i >> 2, c = (i & 3) << 3;
            uint4 vh = make_uint4(0u, 0u, 0u, 0u), vl = vh;
            if (r < avalid) {
                vh = *(const uint4*)(gAh + (size_t)(row0 + r) * K + k0 + c);
                vl = *(const uint4*)(gAl + (size_t)(row0 + r) * K + k0 + c);
            }
            *(uint4*)&sAh[r][c] = vh;
            *(uint4*)&sAl[r][c] = vl;
            uint4 wh = *(const uint4*)(gBh + (size_t)(col0 + r) * K + k0 + c);
            uint4 wl = *(const uint4*)(gBl + (size_t)(col0 + r) * K + k0 + c);
            *(uint4*)&sBh[r][c] = wh;
            *(uint4*)&sBl[r][c] = wl;
        }
        __syncthreads();
        #pragma unroll
        for (int k16 = 0; k16 < GBK / 16; k16++) {
            uint32_t ah[4][4], al[4][4], bh[4][2], bl[4][2];
            #pragma unroll
            for (int mf = 0; mf < 4; mf++) {
                int r = warp_m * 64 + mf * 16 + lar;
                int cc = k16 * 16 + lac;
                ldmat_x4(ah[mf], smem_u32(&sAh[r][cc]));
                ldmat_x4(al[mf], smem_u32(&sAl[r][cc]));
            }
            #pragma unroll
            for (int nf = 0; nf < 4; nf++) {
                int r = warp_n * 32 + nf * 8 + lbr;
                int cc = k16 * 16 + lbc;
                ldmat_x2(bh[nf], smem_u32(&sBh[r][cc]));
                ldmat_x2(bl[nf], smem_u32(&sBl[r][cc]));
            }
            #pragma unroll
            for (int mf = 0; mf < 4; mf++)
                #pragma unroll
                for (int nf = 0; nf < 4; nf++) {
                    mma16816(acc[mf][nf], ah[mf], bh[nf]);
                    mma16816(acc[mf][nf], ah[mf], bl[nf]);
                    mma16816(acc[mf][nf], al[mf], bh[nf]);
                }
        }
    }
    __syncthreads();

    // epilogue: C store + attention dot reduction
    float sa[4][2], da[4][2];
    #pragma unroll
    for (int nf = 0; nf < 4; nf++) {
        int c = warp_n * 32 + nf * 8 + (lane & 3) * 2;
        sa[nf][0] = att_s[hh * CH + c];     sa[nf][1] = att_s[hh * CH + c + 1];
        da[nf][0] = att_d[hh * CH + c];     da[nf][1] = att_d[hh * CH + c + 1];
    }
    #pragma unroll
    for (int mf = 0; mf < 4; mf++) {
        int r0l = warp_m * 64 + mf * 16 + (lane >> 2);
        int r1l = r0l + 8;
        int gr0 = row0 + r0l, gr1 = row0 + r1l;
        float sd0 = 0.f, dd0 = 0.f, sd1 = 0.f, dd1 = 0.f;
        #pragma unroll
        for (int nf = 0; nf < 4; nf++) {
            float c0 = acc[mf][nf][0], c1 = acc[mf][nf][1];
            float c2 = acc[mf][nf][2], c3 = acc[mf][nf][3];
            int gc = col0 + warp_n * 32 + nf * 8 + (lane & 3) * 2;
            if (gr0 < M) *(float2*)&C[(size_t)gr0 * N + gc] = make_float2(c0, c1);
            if (gr1 < M) *(float2*)&C[(size_t)gr1 * N + gc] = make_float2(c2, c3);
            sd0 += c0 * sa[nf][0] + c1 * sa[nf][1];
            dd0 += c0 * da[nf][0] + c1 * da[nf][1];
            sd1 += c2 * sa[nf][0] + c3 * sa[nf][1];
            dd1 += c2 * da[nf][0] + c3 * da[nf][1];
        }
        #pragma unroll
        for (int o = 1; o <= 2; o <<= 1) {
            sd0 += __shfl_xor_sync(0xffffffffu, sd0, o);
            dd0 += __shfl_xor_sync(0xffffffffu, dd0, o);
            sd1 += __shfl_xor_sync(0xffffffffu, sd1, o);
            dd1 += __shfl_xor_sync(0xffffffffu, dd1, o);
        }
        if ((lane & 3) == 0) {
            atomicAdd(&s_sdot[r0l], sd0);
            atomicAdd(&s_ddot[r0l], dd0);
            atomicAdd(&s_sdot[r1l], sd1);
            atomicAdd(&s_ddot[r1l], dd1);
        }
    }
    __syncthreads();
    if (tid < 128 && row0 + tid < M) {
        as_[(row0 + tid) * heads + hh] = s_sdot[tid];
        ad_[(row0 + tid) * heads + hh] = s_ddot[tid];
    }
}

// ---------------- per-dst-node segment softmax (warp per node, CSR) ----------------
template<int HEADS>
__global__ void softmax_kernel(const float* __restrict__ as_, const float* __restrict__ ad_,
                               float* __restrict__ alpha, float* __restrict__ inv)
{
    int warp = (blockIdx.x * blockDim.x + threadIdx.x) >> 5;
    int lane = threadIdx.x & 31;
    if (warp >= NODES) return;
    int node = warp;
    int s0 = g_off[node], s1 = g_off[node + 1];
    #pragma unroll
    for (int hh = 0; hh < HEADS; hh++) {
        float advv = ad_[node * HEADS + hh];
        float mx = -3.4e38f;
        for (int p = s0 + lane; p < s1; p += 32) {
            float v = as_[g_csr_src[p] * HEADS + hh] + advv;
            v = v > 0.f ? v : 0.2f * v;
            mx = fmaxf(mx, v);
        }
        #pragma unroll
        for (int o = 16; o; o >>= 1) mx = fmaxf(mx, __shfl_xor_sync(0xffffffffu, mx, o));
        float sum = 0.f;
        for (int p = s0 + lane; p < s1; p += 32) {
            float v = as_[g_csr_src[p] * HEADS + hh] + advv;
            v = v > 0.f ? v : 0.2f * v;
            float w = __expf(v - mx);
            alpha[(size_t)p * HEADS + hh] = w;
            sum += w;
        }
        #pragma unroll
        for (int o = 16; o; o >>= 1) sum += __shfl_xor_sync(0xffffffffu, sum, o);
        if (lane == 0) inv[node * HEADS + hh] = 1.f / (sum + 1e-16f);
    }
}

// ---------------- conv1 aggregation: block/node, warp/head, bias+ELU -> bf16 hi/lo ----
// edge loop unrolled x4 for memory-level parallelism
__global__ void __launch_bounds__(128)
agg1_kernel(const float* __restrict__ h, const float* __restrict__ alpha,
            const float* __restrict__ inv, const float* __restrict__ bias,
            __nv_bfloat16* __restrict__ outh, __nv_bfloat16* __restrict__ outl)
{
    int node = blockIdx.x;
    int t = threadIdx.x;        // 0..127
    int w = t >> 5;             // head 0..3
    int lane = t & 31;
    int col = w * CH + lane * 4;
    int s0 = g_off[node], s1 = g_off[node + 1];
    float4 acc = make_float4(0.f, 0.f, 0.f, 0.f);
    int p = s0;
    for (; p + 4 <= s1; p += 4) {
        int i0 = g_csr_src[p], i1 = g_csr_src[p + 1];
        int i2 = g_csr_src[p + 2], i3 = g_csr_src[p + 3];
        float a0 = alpha[(size_t)p * H1 + w];
        float a1 = alpha[(size_t)(p + 1) * H1 + w];
        float a2 = alpha[(size_t)(p + 2) * H1 + w];
        float a3 = alpha[(size_t)(p + 3) * H1 + w];
        float4 h0 = *(const float4*)&h[(size_t)i0 * HC1 + col];
        float4 h1 = *(const float4*)&h[(size_t)i1 * HC1 + col];
        float4 h2 = *(const float4*)&h[(size_t)i2 * HC1 + col];
        float4 h3 = *(const float4*)&h[(size_t)i3 * HC1 + col];
        acc.x += a0 * h0.x + a1 * h1.x + a2 * h2.x + a3 * h3.x;
        acc.y += a0 * h0.y + a1 * h1.y + a2 * h2.y + a3 * h3.y;
        acc.z += a0 * h0.z + a1 * h1.z + a2 * h2.z + a3 * h3.z;
        acc.w += a0 * h0.w + a1 * h1.w + a2 * h2.w + a3 * h3.w;
    }
    for (; p < s1; p++) {
        int src = g_csr_src[p];
        float wt = alpha[(size_t)p * H1 + w];
        float4 hv = *(const float4*)&h[(size_t)src * HC1 + col];
        acc.x += wt * hv.x; acc.y += wt * hv.y;
        acc.z += wt * hv.z; acc.w += wt * hv.w;
    }
    float iv = inv[node * H1 + w];
    float4 b = *(const float4*)&bias[col];
    float4 v;
    v.x = acc.x * iv + b.x; v.y = acc.y * iv + b.y;
    v.z = acc.z * iv + b.z; v.w = acc.w * iv + b.w;
    v.x = v.x > 0.f ? v.x : expm1f(v.x);
    v.y = v.y > 0.f ? v.y : expm1f(v.y);
    v.z = v.z > 0.f ? v.z : expm1f(v.z);
    v.w = v.w > 0.f ? v.w : expm1f(v.w);
    size_t o = (size_t)node * HC1 + col;
    __nv_bfloat16 hx, lx;
    split_bf16(v.x, hx, lx); outh[o + 0] = hx; outl[o + 0] = lx;
    split_bf16(v.y, hx, lx); outh[o + 1] = hx; outl[o + 1] = lx;
    split_bf16(v.z, hx, lx); outh[o + 2] = hx; outl[o + 2] = lx;
    split_bf16(v.w, hx, lx); outh[o + 3] = hx; outl[o + 3] = lx;
}

// ---------------- conv2 aggregation: warp per node, fused bias+ELU+maxpool ----------------
__global__ void agg2_pool_kernel(const float* __restrict__ h, const float* __restrict__ alpha,
                                 const float* __restrict__ inv, const float* __restrict__ bias,
                                 const int* __restrict__ batch)
{
    int warp = (blockIdx.x * blockDim.x + threadIdx.x) >> 5;
    int lane = threadIdx.x & 31;
    if (warp >= NODES) return;
    int node = warp;
    int col = lane * 4;
    int s0 = g_off[node], s1 = g_off[node + 1];
    float4 acc = make_float4(0.f, 0.f, 0.f, 0.f);
    int p = s0;
    for (; p + 4 <= s1; p += 4) {
        int i0 = g_csr_src[p], i1 = g_csr_src[p + 1];
        int i2 = g_csr_src[p + 2], i3 = g_csr_src[p + 3];
        float a0 = alpha[p], a1 = alpha[p + 1];
        float a2 = alpha[p + 2], a3 = alpha[p + 3];
        float4 h0 = *(const float4*)&h[(size_t)i0 * CH + col];
        float4 h1 = *(const float4*)&h[(size_t)i1 * CH + col];
        float4 h2 = *(const float4*)&h[(size_t)i2 * CH + col];
        float4 h3 = *(const float4*)&h[(size_t)i3 * CH + col];
        acc.x += a0 * h0.x + a1 * h1.x + a2 * h2.x + a3 * h3.x;
        acc.y += a0 * h0.y + a1 * h1.y + a2 * h2.y + a3 * h3.y;
        acc.z += a0 * h0.z + a1 * h1.z + a2 * h2.z + a3 * h3.z;
        acc.w += a0 * h0.w + a1 * h1.w + a2 * h2.w + a3 * h3.w;
    }
    for (; p < s1; p++) {
        int src = g_csr_src[p];
        float wt = alpha[p];
        float4 hv = *(const float4*)&h[(size_t)src * CH + col];
        acc.x += wt * hv.x; acc.y += wt * hv.y;
        acc.z += wt * hv.z; acc.w += wt * hv.w;
    }
    float iv = inv[node];
    float4 b = *(const float4*)&bias[col];
    float4 v;
    v.x = acc.x * iv + b.x; v.y = acc.y * iv + b.y;
    v.z = acc.z * iv + b.z; v.w = acc.w * iv + b.w;
    v.x = v.x > 0.f ? v.x : expm1f(v.x);
    v.y = v.y > 0.f ? v.y : expm1f(v.y);
    v.z = v.z > 0.f ? v.z : expm1f(v.z);
    v.w = v.w > 0.f ? v.w : expm1f(v.w);
    float* pp = &g_pool[batch[node] * CH + col];
    atomicMaxF(pp + 0, v.x);
    atomicMaxF(pp + 1, v.y);
    atomicMaxF(pp + 2, v.z);
    atomicMaxF(pp + 3, v.w);
}

// ---------------- classifier head ----------------
__global__ void classify_kernel(const float* __restrict__ Wc1, const float* __restrict__ bc1,
                                const float* __restrict__ Wc2, const float* __restrict__ bc2,
                                float* __restrict__ out)
{
    __shared__ float xp[CH];
    __shared__ float hc[CH / 2];
    int gg = blockIdx.x;
    int t = threadIdx.x;   // 0..63
    xp[t]      = g_pool[gg * CH + t];
    xp[t + 64] = g_pool[gg * CH + 64 + t];
    __syncthreads();
    float acc = bc1[t];
    for (int k = 0; k < CH; k++) acc += xp[k] * Wc1[k * (CH / 2) + t];
    hc[t] = fmaxf(acc, 0.f);
    __syncthreads();
    if (t < NCLS) {
        float o = bc2[t];
        for (int k = 0; k < CH / 2; k++) o += hc[k] * Wc2[k * NCLS + t];
        out[gg * NCLS + t] = o;
    }
}

// ---------------- launch ----------------
extern "C" void kernel_launch(void* const* d_in, const int* in_sizes, int n_in,
                              void* d_out, int out_size)
{
    const float* xs    = (const float*)d_in[0];
    const int*   xop   = (const int*)d_in[1];
    const int*   xsrc  = (const int*)d_in[2];
    const int*   xsink = (const int*)d_in[3];
    const int*   xstr  = (const int*)d_in[4];
    const int*   xpay  = (const int*)d_in[5];
    const int*   ei    = (const int*)d_in[6];
    const int*   batch = (const int*)d_in[7];
    const float* eop   = (const float*)d_in[8];
    const float* esrc  = (const float*)d_in[9];
    const float* esink = (const float*)d_in[10];
    const float* estr  = (const float*)d_in[11];
    const float* epay  = (const float*)d_in[12];
    const float* lng   = (const float*)d_in[13];
    const float* lnb   = (const float*)d_in[14];
    const float* W1    = (const float*)d_in[15];
    const float* att_s1= (const float*)d_in[16];
    const float* att_d1= (const float*)d_in[17];
    const float* b1    = (const float*)d_in[18];
    const float* W2    = (const float*)d_in[19];
    const float* att_s2= (const float*)d_in[20];
    const float* att_d2= (const float*)d_in[21];
    const float* b2    = (const float*)d_in[22];
    const float* Wc1   = (const float*)d_in[23];
    const float* bc1   = (const float*)d_in[24];
    const float* Wc2   = (const float*)d_in[25];
    const float* bc2   = (const float*)d_in[26];
    float* out = (float*)d_out;

    __nv_bfloat16 *fh, *fl, *w1th, *w1tl, *w2th, *w2tl, *o1h, *o1l;
    float *h1, *as1, *ad1, *inv1, *alpha1;
    float *h2, *as2, *ad2, *inv2, *alpha2;
    cudaGetSymbolAddress((void**)&fh,    g_fh);
    cudaGetSymbolAddress((void**)&fl,    g_fl);
    cudaGetSymbolAddress((void**)&w1th,  g_w1th);
    cudaGetSymbolAddress((void**)&w1tl,  g_w1tl);
    cudaGetSymbolAddress((void**)&w2th,  g_w2th);
    cudaGetSymbolAddress((void**)&w2tl,  g_w2tl);
    cudaGetSymbolAddress((void**)&o1h,   g_o1h);
    cudaGetSymbolAddress((void**)&o1l,   g_o1l);
    cudaGetSymbolAddress((void**)&h1,    g_h1);
    cudaGetSymbolAddress((void**)&as1,   g_as1);
    cudaGetSymbolAddress((void**)&ad1,   g_ad1);
    cudaGetSymbolAddress((void**)&inv1,  g_inv1);
    cudaGetSymbolAddress((void**)&alpha1,g_alpha1);
    cudaGetSymbolAddress((void**)&h2,    g_h2);
    cudaGetSymbolAddress((void**)&as2,   g_as2);
    cudaGetSymbolAddress((void**)&ad2,   g_ad2);
    cudaGetSymbolAddress((void**)&inv2,  g_inv2);
    cudaGetSymbolAddress((void**)&alpha2,g_alpha2);

    auto blocks = [](long long n, int bs) { return (unsigned)((n + bs - 1) / bs); };

    // fused scratch init (deg, pos, pool)
    init_kernel<<<blocks(NODES, 256), 256>>>();

    // CSR build
    deg_kernel<<<blocks(EP, 256), 256>>>(ei);
    scan_kernel<<<1, 1024>>>();
    scatter_kernel<<<blocks(EP, 256), 256>>>(ei);

    // fused weight transposes + splits
    prep_w_kernel<<<blocks((long long)(IN_DIM * HC1 + HC1 * CH), 256), 256>>>(W1, W2);

    // 1. features + layernorm -> bf16 hi/lo
    build_feats_kernel<<<NODES, 256>>>(xs, xop, xsrc, xsink, xstr, xpay,
                                       eop, esrc, esink, estr, epay, lng, lnb);

    // 2. conv1: HMMA GEMM (+fused attn scores), softmax, aggregate
    {
        dim3 grid(HC1 / 128, (NODES + 127) / 128);
        gemm_bf3_kernel<<<grid, 256>>>(fh, fl, w1th, w1tl, h1,
                                       att_s1, att_d1, as1, ad1,
                                       NODES, HC1, IN_DIM, H1);
    }
    softmax_kernel<H1><<<blocks((long long)NODES * 32, 256), 256>>>(as1, ad1, alpha1, inv1);
    agg1_kernel<<<NODES, 128>>>(h1, alpha1, inv1, b1, o1h, o1l);

    // 3. conv2
    {
        dim3 grid(CH / 128, (NODES + 127) / 128);
        gemm_bf3_kernel<<<grid, 256>>>(o1h, o1l, w2th, w2tl, h2,
                                       att_s2, att_d2, as2, ad2,
                                       NODES, CH, HC1, 1);
    }
    softmax_kernel<1><<<blocks((long long)NODES * 32, 256), 256>>>(as2, ad2, alpha2, inv2);
    agg2_pool_kernel<<<blocks((long long)NODES * 32, 256), 256>>>(h2, alpha2, inv2, b2, batch);

    // 4. classifier
    classify_kernel<<<NGRAPH, 64>>>(Wc1, bc1, Wc2, bc2, out);
}